// round 15
// baseline (speedup 1.0000x reference)
#include <cuda_runtime.h>
#include <cstdint>
#include <cstddef>

#define B_   2048
#define E_   512
#define EMB_ 256
#define AR_  1024
#define H256_ 256
#define H32_  32
#define NT_   256
#define NG_   128   // u-partial groups (8 ar-dims each)

// Scratch (no cudaMalloc allowed)
__device__ float g_t[B_ * H256_];          // relu(mask@W_func + b_func)
__device__ float g_bvec[H32_];             // b_fc1 @ W_fc2 + b_fc2
__device__ float g_up[(size_t)B_ * NG_ * H32_];  // u-partials [b][g][lane], 33.5MB

// ---------------------------------------------------------------------------
// Threefry2x32-20, JAX partitionable variant: counter (hi=0, lo=index),
// output = out0 ^ out1, key = (0, 42).
// ---------------------------------------------------------------------------
__device__ __forceinline__ uint32_t rotl32(uint32_t x, int r) {
    return (x << r) | (x >> (32 - r));
}

__device__ __forceinline__ uint32_t threefry_bits(uint32_t k0, uint32_t k1,
                                                  uint32_t c0, uint32_t c1) {
    uint32_t ks2 = k0 ^ k1 ^ 0x1BD11BDAu;
    uint32_t x0 = c0 + k0;
    uint32_t x1 = c1 + k1;
#define TF_RND(r) { x0 += x1; x1 = rotl32(x1, (r)); x1 ^= x0; }
    TF_RND(13) TF_RND(15) TF_RND(26) TF_RND(6)
    x0 += k1;  x1 += ks2 + 1u;
    TF_RND(17) TF_RND(29) TF_RND(16) TF_RND(24)
    x0 += ks2; x1 += k0 + 2u;
    TF_RND(13) TF_RND(15) TF_RND(26) TF_RND(6)
    x0 += k0;  x1 += k1 + 3u;
    TF_RND(17) TF_RND(29) TF_RND(16) TF_RND(24)
    x0 += k1;  x1 += ks2 + 4u;
    TF_RND(13) TF_RND(15) TF_RND(26) TF_RND(6)
    x0 += ks2; x1 += k0 + 5u;
#undef TF_RND
    return x0 ^ x1;
}

__device__ __forceinline__ float gumbel_from_index(uint32_t idx) {
    uint32_t bits = threefry_bits(0u, 42u, 0u, idx);
    float u = __uint_as_float((bits >> 9) | 0x3f800000u) - 1.0f;
    const float tiny = 1.17549435e-38f;
    u = fmaxf(tiny, u + tiny);
    return -logf(-logf(u));
}

// ---------------------------------------------------------------------------
// J: one launch, two independent jobs.
//   blocks [0,256):   g_t = relu(maskf @ W_func + b_func)   (BM32/BN64/BK32)
//   blocks [256,384): g = bid-256. Warp i computes W12 row 8g+i (in smem),
//                     then all warps compute rank-8 u-partials
//                     g_up[b][g][:] = ar[b][8g..8g+8] @ W12rows for all b.
//                     Block 256 warp 0 also computes g_bvec.
// ---------------------------------------------------------------------------
__global__ __launch_bounds__(256)
void kernelJ(const float* __restrict__ ar, const int* __restrict__ utm,
             const float* __restrict__ W_func, const float* __restrict__ b_func,
             const float* __restrict__ W_fc1, const float* __restrict__ W_fc2,
             const float* __restrict__ b_fc1, const float* __restrict__ b_fc2) {
    const int bid = blockIdx.x;
    const int tid = threadIdx.x;

    if (bid < 256) {
        __shared__ float As[32][33];
        __shared__ float Bs[32][64];

        const int bm = (bid & 63) * 32;
        const int bn = (bid >> 6) * 64;
        const int tx = tid & 15;
        const int ty = tid >> 4;
        const int lAr = tid >> 3;
        const int lAk = (tid & 7) * 4;

        float acc[2][4];
#pragma unroll
        for (int i = 0; i < 2; i++)
#pragma unroll
            for (int j = 0; j < 4; j++) acc[i][j] = 0.0f;

        for (int k0 = 0; k0 < NT_; k0 += 32) {
            int4 mi = *(const int4*)(utm + (bm + lAr) * NT_ + k0 + lAk);
            As[lAk + 0][lAr] = (float)mi.x;
            As[lAk + 1][lAr] = (float)mi.y;
            As[lAk + 2][lAr] = (float)mi.z;
            As[lAk + 3][lAr] = (float)mi.w;
#pragma unroll
            for (int i = 0; i < 2; i++) {
                int f = tid + i * 256;
                int kr = f >> 4, c = (f & 15) * 4;
                *(float4*)&Bs[kr][c] =
                    *(const float4*)(W_func + (size_t)(k0 + kr) * H256_ + bn + c);
            }
            __syncthreads();
#pragma unroll
            for (int kk = 0; kk < 32; kk++) {
                float a0 = As[kk][ty * 2];
                float a1 = As[kk][ty * 2 + 1];
                float4 b4 = *(const float4*)&Bs[kk][tx * 4];
                acc[0][0] += a0 * b4.x; acc[0][1] += a0 * b4.y;
                acc[0][2] += a0 * b4.z; acc[0][3] += a0 * b4.w;
                acc[1][0] += a1 * b4.x; acc[1][1] += a1 * b4.y;
                acc[1][2] += a1 * b4.z; acc[1][3] += a1 * b4.w;
            }
            __syncthreads();
        }

#pragma unroll
        for (int i = 0; i < 2; i++) {
            const int row = bm + ty * 2 + i;
#pragma unroll
            for (int j = 0; j < 4; j++) {
                const int col = bn + tx * 4 + j;
                g_t[row * H256_ + col] = fmaxf(acc[i][j] + b_func[col], 0.0f);
            }
        }
    } else {
        // ---------------- W12 rows (smem) + u-partials ----------------
        const int g = bid - 256;              // 0..127
        const int warp = tid >> 5;
        const int lane = tid & 31;
        __shared__ float s_w12[8][32];

        // W12 row r = 8g + warp: lane j gets sum_k W_fc1[r][k] * W_fc2[k][j]
        {
            const int r = g * 8 + warp;
            const float* frow = W_fc1 + (size_t)r * H256_;
            float a0 = 0.f, a1 = 0.f, a2 = 0.f, a3 = 0.f;
#pragma unroll 8
            for (int k = 0; k < H256_; k += 4) {
                float4 f = *(const float4*)(frow + k);
                a0 += f.x * W_fc2[(k + 0) * H32_ + lane];
                a1 += f.y * W_fc2[(k + 1) * H32_ + lane];
                a2 += f.z * W_fc2[(k + 2) * H32_ + lane];
                a3 += f.w * W_fc2[(k + 3) * H32_ + lane];
            }
            s_w12[warp][lane] = (a0 + a1) + (a2 + a3);
        }
        if (g == 0 && warp == 0) {
            float b0 = b_fc2[lane];
#pragma unroll 8
            for (int k = 0; k < H256_; k++) b0 += b_fc1[k] * W_fc2[k * H32_ + lane];
            g_bvec[lane] = b0;
        }
        __syncthreads();

        // Hoist the 8 W12 values for this lane into registers.
        float w12r[8];
#pragma unroll
        for (int i = 0; i < 8; i++) w12r[i] = s_w12[i][lane];

        // u-partials: warp handles b in [warp*256, warp*256+256).
        const int bstart = warp * 256;
        const float* arp = ar + (size_t)bstart * AR_ + g * 8;
        float* upp = g_up + ((size_t)bstart * NG_ + g) * H32_ + lane;
#pragma unroll 2
        for (int bb = 0; bb < 256; bb++) {
            const float4 x0 = *(const float4*)(arp + (size_t)bb * AR_);
            const float4 x1 = *(const float4*)(arp + (size_t)bb * AR_ + 4);
            float p = x0.x * w12r[0] + x0.y * w12r[1]
                    + x0.z * w12r[2] + x0.w * w12r[3]
                    + x1.x * w12r[4] + x1.y * w12r[5]
                    + x1.z * w12r[6] + x1.w * w12r[7];
            upp[(size_t)bb * NG_ * H32_] = p;
        }
    }
}

// ---------------------------------------------------------------------------
// BFS2: fused, 2 b's per block, grid 1024. Slim prologue (R8-BFS proven):
// load t; z2 partials = t@W_fc2 (per-warp 32 rows) + u-partial sums
// (per-warp 16 contiguous 128B chunks per b); LSTM (+bvec); w = W_conv@q.
// Then the proven ee stream. Natural register allocation (no launch_bounds
// cap beyond 256 threads — 56 regs / 4 blocks/SM is the measured-best shape).
// ---------------------------------------------------------------------------
__global__ __launch_bounds__(256)
void kernelBFS2(const int* __restrict__ tum, const float* __restrict__ ee,
                const float* __restrict__ W_conv, const float* __restrict__ b_conv,
                const float* __restrict__ W_fc2,
                const float* __restrict__ lk, const float* __restrict__ lb,
                float* __restrict__ out, int mode) {
    const int b0 = blockIdx.x * 2;
    const int tid = threadIdx.x;
    const int warp = tid >> 5;
    const int lane = tid & 31;

    __shared__ float s_t[2][H256_];
    __shared__ float s_p[2][8][32];
    __shared__ float s_q[2][32];
    __shared__ float s_w[2][EMB_];
    __shared__ float s_c0[2];
    __shared__ float ys[512];
    __shared__ float wred[8];
    __shared__ float wred2[8];
    __shared__ float wv[8];
    __shared__ int   wi[8];

    // ---- load t ----
    s_t[0][tid] = g_t[(b0 + 0) * H256_ + tid];
    s_t[1][tid] = g_t[(b0 + 1) * H256_ + tid];
    __syncthreads();

    // ---- z2 partials: t@W_fc2 (warp's 32 rows) + u-partial sums ----
    {
        float p0 = 0.f, p1 = 0.f;
#pragma unroll
        for (int jj = 0; jj < 32; jj++) {
            const int j = warp * 32 + jj;
            const float wf = W_fc2[j * H32_ + lane];
            p0 += s_t[0][j] * wf;
            p1 += s_t[1][j] * wf;
        }
        // u-partials: warp sums g = warp*16 .. +15 for both b's.
        // Layout [b][g][lane]: 16 consecutive 128B chunks = 2KB contiguous.
        const float* up0 = g_up + ((size_t)(b0 + 0) * NG_ + warp * 16) * H32_ + lane;
        const float* up1 = g_up + ((size_t)(b0 + 1) * NG_ + warp * 16) * H32_ + lane;
        float ua0 = 0.f, ua1 = 0.f, ub0 = 0.f, ub1 = 0.f;
#pragma unroll
        for (int k = 0; k < 16; k += 2) {
            ua0 += up0[(size_t)(k + 0) * H32_];
            ua1 += up0[(size_t)(k + 1) * H32_];
            ub0 += up1[(size_t)(k + 0) * H32_];
            ub1 += up1[(size_t)(k + 1) * H32_];
        }
        s_p[0][warp][lane] = p0 + (ua0 + ua1);
        s_p[1][warp][lane] = p1 + (ub0 + ub1);
    }
    __syncthreads();

    // ---- LSTM: warp q in {0,1}; z = bvec + partial sums ----
    if (warp < 2) {
        float z = g_bvec[lane];
#pragma unroll
        for (int w2 = 0; w2 < 8; w2++) z += s_p[warp][w2][lane];
        float zi = lb[lane];
        float zg = lb[64 + lane];
        float zo = lb[96 + lane];
#pragma unroll
        for (int m = 0; m < 32; m++) {
            float v = __shfl_sync(0xffffffffu, z, m);
            zi += v * lk[m * 128 + lane];
            zg += v * lk[m * 128 + 64 + lane];
            zo += v * lk[m * 128 + 96 + lane];
        }
        float ig = 1.0f / (1.0f + expf(-zi));
        float gg = tanhf(zg);
        float og = 1.0f / (1.0f + expf(-zo));
        float c  = ig * gg;
        float h  = og * tanhf(c);
        s_q[warp][lane] = h;
        float part = b_conv[lane] * h;
#pragma unroll
        for (int s = 16; s > 0; s >>= 1) part += __shfl_xor_sync(0xffffffffu, part, s);
        if (lane == 0) s_c0[warp] = part;
    }
    __syncthreads();

    // ---- w = W_conv @ q, row per thread, shared across both b's ----
    {
        const float* wr = W_conv + tid * H32_;
        float4 wc[8];
#pragma unroll
        for (int m = 0; m < 8; m++) wc[m] = *(const float4*)(wr + m * 4);
#pragma unroll
        for (int q = 0; q < 2; q++) {
            float s0 = 0.f, s1 = 0.f;
#pragma unroll
            for (int m = 0; m < 8; m++) {
                s0 += wc[m].x * s_q[q][m * 4 + 0] + wc[m].y * s_q[q][m * 4 + 1];
                s1 += wc[m].z * s_q[q][m * 4 + 2] + wc[m].w * s_q[q][m * 4 + 3];
            }
            s_w[q][tid] = s0 + s1;
        }
    }
    __syncthreads();

    // =========================== Stream both b's ===========================
    for (int q = 0; q < 2; q++) {
        const int b = b0 + q;
        const float4 w0 = *(const float4*)(&s_w[q][4 * lane]);
        const float4 w1 = *(const float4*)(&s_w[q][128 + 4 * lane]);
        const float cb = s_c0[q];
        const int tm = tum[b];
        const float4* eb = (const float4*)(ee + (size_t)b * E_ * EMB_);

#pragma unroll
        for (int it = 0; it < 16; it++) {
            const int e0 = it * 32 + warp * 4;
            float4 r0a = __ldcs(eb + (size_t)(e0 + 0) * 64 + lane);
            float4 r0b = __ldcs(eb + (size_t)(e0 + 0) * 64 + 32 + lane);
            float4 r1a = __ldcs(eb + (size_t)(e0 + 1) * 64 + lane);
            float4 r1b = __ldcs(eb + (size_t)(e0 + 1) * 64 + 32 + lane);
            float4 r2a = __ldcs(eb + (size_t)(e0 + 2) * 64 + lane);
            float4 r2b = __ldcs(eb + (size_t)(e0 + 2) * 64 + 32 + lane);
            float4 r3a = __ldcs(eb + (size_t)(e0 + 3) * 64 + lane);
            float4 r3b = __ldcs(eb + (size_t)(e0 + 3) * 64 + 32 + lane);

            float s0 = r0a.x * w0.x + r0a.y * w0.y + r0a.z * w0.z + r0a.w * w0.w
                     + r0b.x * w1.x + r0b.y * w1.y + r0b.z * w1.z + r0b.w * w1.w;
            float s1 = r1a.x * w0.x + r1a.y * w0.y + r1a.z * w0.z + r1a.w * w0.w
                     + r1b.x * w1.x + r1b.y * w1.y + r1b.z * w1.z + r1b.w * w1.w;
            float s2 = r2a.x * w0.x + r2a.y * w0.y + r2a.z * w0.z + r2a.w * w0.w
                     + r2b.x * w1.x + r2b.y * w1.y + r2b.z * w1.z + r2b.w * w1.w;
            float s3 = r3a.x * w0.x + r3a.y * w0.y + r3a.z * w0.z + r3a.w * w0.w
                     + r3b.x * w1.x + r3b.y * w1.y + r3b.z * w1.z + r3b.w * w1.w;
#pragma unroll
            for (int o = 16; o > 0; o >>= 1) {
                s0 += __shfl_xor_sync(0xffffffffu, s0, o);
                s1 += __shfl_xor_sync(0xffffffffu, s1, o);
                s2 += __shfl_xor_sync(0xffffffffu, s2, o);
                s3 += __shfl_xor_sync(0xffffffffu, s3, o);
            }
            if (lane == 0) {
                ys[e0 + 0] = s0 + cb;
                ys[e0 + 1] = s1 + cb;
                ys[e0 + 2] = s2 + cb;
                ys[e0 + 3] = s3 + cb;
            }
        }
        __syncthreads();

        const float y0 = ys[tid];
        const float y1 = ys[tid + 256];

        // masked logit stores: fire-and-forget
        const float mf = (float)tm;
        out[(size_t)b * 512 + tid]       = y0 * mf;
        out[(size_t)b * 512 + tid + 256] = y1 * mf;

        // gumbel noise (pure ALU)
        const float gb0 = gumbel_from_index((uint32_t)(b * 512 + tid));
        const float gb1 = gumbel_from_index((uint32_t)(b * 512 + tid + 256));

        // ---- max ----
        float m = fmaxf(y0, y1);
#pragma unroll
        for (int o = 16; o > 0; o >>= 1) m = fmaxf(m, __shfl_xor_sync(0xffffffffu, m, o));
        if (lane == 0) wred[warp] = m;
        __syncthreads();
        float maxv = wred[0];
#pragma unroll
        for (int i2 = 1; i2 < 8; i2++) maxv = fmaxf(maxv, wred[i2]);

        // ---- exp + sum ----
        const float e0v = expf(y0 - maxv);
        const float e1v = expf(y1 - maxv);
        float s = e0v + e1v;
#pragma unroll
        for (int o = 16; o > 0; o >>= 1) s += __shfl_xor_sync(0xffffffffu, s, o);
        if (lane == 0) wred2[warp] = s;
        __syncthreads();
        float sumv = wred2[0];
#pragma unroll
        for (int i2 = 1; i2 < 8; i2++) sumv += wred2[i2];

        if (mode != 0) {
            const float sc0 = e0v / sumv + gb0;
            const float sc1 = e1v / sumv + gb1;
            float bv; int bi;
            if (sc1 > sc0) { bv = sc1; bi = tid + 256; } else { bv = sc0; bi = tid; }
#pragma unroll
            for (int o = 16; o > 0; o >>= 1) {
                float ov = __shfl_xor_sync(0xffffffffu, bv, o);
                int   oi = __shfl_xor_sync(0xffffffffu, bi, o);
                if (ov > bv || (ov == bv && oi < bi)) { bv = ov; bi = oi; }
            }
            if (lane == 0) { wv[warp] = bv; wi[warp] = bi; }
            __syncthreads();
            if (tid == 0) {
                float fv = wv[0]; int fi = wi[0];
#pragma unroll
                for (int i2 = 1; i2 < 8; i2++) {
                    if (wv[i2] > fv || (wv[i2] == fv && wi[i2] < fi)) { fv = wv[i2]; fi = wi[i2]; }
                }
                long long id = (long long)fi * (long long)tm;
                if (mode == 1) out[1048576 + b] = (float)id;
                else ((long long*)(out + 1048576))[b] = id;
            }
        }
        __syncthreads();   // protect ys / wred reuse for next q
    }
}

// ---------------------------------------------------------------------------
extern "C" void kernel_launch(void* const* d_in, const int* in_sizes, int n_in,
                              void* d_out, int out_size) {
    const float* ar     = (const float*)d_in[0];
    const int*   utm    = (const int*)d_in[1];
    const int*   tum    = (const int*)d_in[2];
    const float* ee     = (const float*)d_in[3];
    const float* W_func = (const float*)d_in[4];
    const float* b_func = (const float*)d_in[5];
    const float* W_conv = (const float*)d_in[6];
    const float* b_conv = (const float*)d_in[7];
    const float* W_fc1  = (const float*)d_in[8];
    const float* b_fc1  = (const float*)d_in[9];
    const float* W_fc2  = (const float*)d_in[10];
    const float* b_fc2  = (const float*)d_in[11];
    const float* lk     = (const float*)d_in[12];
    // d_in[13] = lstm_recurrent: unused (h0 = 0)
    const float* lb     = (const float*)d_in[14];

    kernelJ<<<384, 256>>>(ar, utm, W_func, b_func, W_fc1, W_fc2, b_fc1, b_fc2);

    int mode = 0;
    if (out_size >= 1048576 + 4096)      mode = 2;
    else if (out_size >= 1048576 + 2048) mode = 1;
    kernelBFS2<<<1024, 256>>>(tum, ee, W_conv, b_conv, W_fc2,
                              lk, lb, (float*)d_out, mode);
}

// round 16
// speedup vs baseline: 1.0852x; 1.0852x over previous
#include <cuda_runtime.h>
#include <cstdint>
#include <cstddef>

#define B_   2048
#define E_   512
#define EMB_ 256
#define AR_  1024
#define H256_ 256
#define H32_  32
#define NT_   256
#define NG_   128   // u-partial groups (8 ar-dims each)

// Scratch (no cudaMalloc allowed)
__device__ float g_t[B_ * H256_];          // relu(mask@W_func + b_func)
__device__ float g_bvec[H32_];             // b_fc1 @ W_fc2 + b_fc2
__device__ float g_up[(size_t)B_ * NG_ * H32_];  // u-partials [b][g][lane], 33.5MB

// ---------------------------------------------------------------------------
// Threefry2x32-20, JAX partitionable variant: counter (hi=0, lo=index),
// output = out0 ^ out1, key = (0, 42).
// ---------------------------------------------------------------------------
__device__ __forceinline__ uint32_t rotl32(uint32_t x, int r) {
    return (x << r) | (x >> (32 - r));
}

__device__ __forceinline__ uint32_t threefry_bits(uint32_t k0, uint32_t k1,
                                                  uint32_t c0, uint32_t c1) {
    uint32_t ks2 = k0 ^ k1 ^ 0x1BD11BDAu;
    uint32_t x0 = c0 + k0;
    uint32_t x1 = c1 + k1;
#define TF_RND(r) { x0 += x1; x1 = rotl32(x1, (r)); x1 ^= x0; }
    TF_RND(13) TF_RND(15) TF_RND(26) TF_RND(6)
    x0 += k1;  x1 += ks2 + 1u;
    TF_RND(17) TF_RND(29) TF_RND(16) TF_RND(24)
    x0 += ks2; x1 += k0 + 2u;
    TF_RND(13) TF_RND(15) TF_RND(26) TF_RND(6)
    x0 += k0;  x1 += k1 + 3u;
    TF_RND(17) TF_RND(29) TF_RND(16) TF_RND(24)
    x0 += k1;  x1 += ks2 + 4u;
    TF_RND(13) TF_RND(15) TF_RND(26) TF_RND(6)
    x0 += ks2; x1 += k0 + 5u;
#undef TF_RND
    return x0 ^ x1;
}

__device__ __forceinline__ float gumbel_from_index(uint32_t idx) {
    uint32_t bits = threefry_bits(0u, 42u, 0u, idx);
    float u = __uint_as_float((bits >> 9) | 0x3f800000u) - 1.0f;
    const float tiny = 1.17549435e-38f;
    u = fmaxf(tiny, u + tiny);
    return -logf(-logf(u));
}

// ---------------------------------------------------------------------------
// J: one launch, two independent jobs. grid = 512.
//   blocks [0,256):   g_t = relu(maskf @ W_func + b_func)   (BM32/BN64/BK32)
//   blocks [256,512): ub = bid-256; g = ub>>1; half = ub&1.
//                     Warp i computes W12 row 8g+i (smem, redundant per pair),
//                     then each warp computes rank-8 u-partials for 128 b's
//                     (b = half*1024 + warp*128 ..+128), unroll 8.
// ---------------------------------------------------------------------------
__global__ __launch_bounds__(256)
void kernelJ(const float* __restrict__ ar, const int* __restrict__ utm,
             const float* __restrict__ W_func, const float* __restrict__ b_func,
             const float* __restrict__ W_fc1, const float* __restrict__ W_fc2,
             const float* __restrict__ b_fc1, const float* __restrict__ b_fc2) {
    const int bid = blockIdx.x;
    const int tid = threadIdx.x;

    if (bid < 256) {
        __shared__ float As[32][33];
        __shared__ float Bs[32][64];

        const int bm = (bid & 63) * 32;
        const int bn = (bid >> 6) * 64;
        const int tx = tid & 15;
        const int ty = tid >> 4;
        const int lAr = tid >> 3;
        const int lAk = (tid & 7) * 4;

        float acc[2][4];
#pragma unroll
        for (int i = 0; i < 2; i++)
#pragma unroll
            for (int j = 0; j < 4; j++) acc[i][j] = 0.0f;

        for (int k0 = 0; k0 < NT_; k0 += 32) {
            int4 mi = *(const int4*)(utm + (bm + lAr) * NT_ + k0 + lAk);
            As[lAk + 0][lAr] = (float)mi.x;
            As[lAk + 1][lAr] = (float)mi.y;
            As[lAk + 2][lAr] = (float)mi.z;
            As[lAk + 3][lAr] = (float)mi.w;
#pragma unroll
            for (int i = 0; i < 2; i++) {
                int f = tid + i * 256;
                int kr = f >> 4, c = (f & 15) * 4;
                *(float4*)&Bs[kr][c] =
                    *(const float4*)(W_func + (size_t)(k0 + kr) * H256_ + bn + c);
            }
            __syncthreads();
#pragma unroll
            for (int kk = 0; kk < 32; kk++) {
                float a0 = As[kk][ty * 2];
                float a1 = As[kk][ty * 2 + 1];
                float4 b4 = *(const float4*)&Bs[kk][tx * 4];
                acc[0][0] += a0 * b4.x; acc[0][1] += a0 * b4.y;
                acc[0][2] += a0 * b4.z; acc[0][3] += a0 * b4.w;
                acc[1][0] += a1 * b4.x; acc[1][1] += a1 * b4.y;
                acc[1][2] += a1 * b4.z; acc[1][3] += a1 * b4.w;
            }
            __syncthreads();
        }

#pragma unroll
        for (int i = 0; i < 2; i++) {
            const int row = bm + ty * 2 + i;
#pragma unroll
            for (int j = 0; j < 4; j++) {
                const int col = bn + tx * 4 + j;
                g_t[row * H256_ + col] = fmaxf(acc[i][j] + b_func[col], 0.0f);
            }
        }
    } else {
        // ---------------- W12 rows (smem) + u-partials ----------------
        const int ub = bid - 256;            // 0..255
        const int g = ub >> 1;               // 0..127
        const int half = ub & 1;             // b-range half
        const int warp = tid >> 5;
        const int lane = tid & 31;
        __shared__ float s_w12[8][32];

        // W12 row r = 8g + warp (redundant across the block pair — cheap)
        {
            const int r = g * 8 + warp;
            const float* frow = W_fc1 + (size_t)r * H256_;
            float a0 = 0.f, a1 = 0.f, a2 = 0.f, a3 = 0.f;
#pragma unroll 8
            for (int k = 0; k < H256_; k += 4) {
                float4 f = *(const float4*)(frow + k);
                a0 += f.x * W_fc2[(k + 0) * H32_ + lane];
                a1 += f.y * W_fc2[(k + 1) * H32_ + lane];
                a2 += f.z * W_fc2[(k + 2) * H32_ + lane];
                a3 += f.w * W_fc2[(k + 3) * H32_ + lane];
            }
            s_w12[warp][lane] = (a0 + a1) + (a2 + a3);
        }
        if (ub == 0 && warp == 0) {
            float b0 = b_fc2[lane];
#pragma unroll 8
            for (int k = 0; k < H256_; k++) b0 += b_fc1[k] * W_fc2[k * H32_ + lane];
            g_bvec[lane] = b0;
        }
        __syncthreads();

        // Hoist this lane's 8 W12 values.
        float w12r[8];
#pragma unroll
        for (int i = 0; i < 8; i++) w12r[i] = s_w12[i][lane];

        // u-partials: 128 b's per warp, unroll 8 (16 independent LDG.128
        // in flight, then 8 independent stores).
        const int bstart = half * 1024 + warp * 128;
        const float* arp = ar + (size_t)bstart * AR_ + g * 8;
        float* upp = g_up + ((size_t)bstart * NG_ + g) * H32_ + lane;
        for (int bb0 = 0; bb0 < 128; bb0 += 8) {
            float p[8];
#pragma unroll
            for (int i = 0; i < 8; i++) {
                const size_t off = (size_t)(bb0 + i) * AR_;
                const float4 x0 = *(const float4*)(arp + off);
                const float4 x1 = *(const float4*)(arp + off + 4);
                p[i] = x0.x * w12r[0] + x0.y * w12r[1]
                     + x0.z * w12r[2] + x0.w * w12r[3]
                     + x1.x * w12r[4] + x1.y * w12r[5]
                     + x1.z * w12r[6] + x1.w * w12r[7];
            }
#pragma unroll
            for (int i = 0; i < 8; i++)
                upp[(size_t)(bb0 + i) * NG_ * H32_] = p[i];
        }
    }
}

// ---------------------------------------------------------------------------
// BFS2: fused, 2 b's per block, grid 1024. (Byte-identical to R15 — measured
// 173.8us @ 80.8% DRAM.) Slim prologue: load t; z2 partials = t@W_fc2 +
// u-partial sums; LSTM (+bvec); w = W_conv@q. Then the proven ee stream.
// ---------------------------------------------------------------------------
__global__ __launch_bounds__(256)
void kernelBFS2(const int* __restrict__ tum, const float* __restrict__ ee,
                const float* __restrict__ W_conv, const float* __restrict__ b_conv,
                const float* __restrict__ W_fc2,
                const float* __restrict__ lk, const float* __restrict__ lb,
                float* __restrict__ out, int mode) {
    const int b0 = blockIdx.x * 2;
    const int tid = threadIdx.x;
    const int warp = tid >> 5;
    const int lane = tid & 31;

    __shared__ float s_t[2][H256_];
    __shared__ float s_p[2][8][32];
    __shared__ float s_q[2][32];
    __shared__ float s_w[2][EMB_];
    __shared__ float s_c0[2];
    __shared__ float ys[512];
    __shared__ float wred[8];
    __shared__ float wred2[8];
    __shared__ float wv[8];
    __shared__ int   wi[8];

    // ---- load t ----
    s_t[0][tid] = g_t[(b0 + 0) * H256_ + tid];
    s_t[1][tid] = g_t[(b0 + 1) * H256_ + tid];
    __syncthreads();

    // ---- z2 partials: t@W_fc2 (warp's 32 rows) + u-partial sums ----
    {
        float p0 = 0.f, p1 = 0.f;
#pragma unroll
        for (int jj = 0; jj < 32; jj++) {
            const int j = warp * 32 + jj;
            const float wf = W_fc2[j * H32_ + lane];
            p0 += s_t[0][j] * wf;
            p1 += s_t[1][j] * wf;
        }
        // u-partials: warp sums g = warp*16 .. +15 for both b's.
        const float* up0 = g_up + ((size_t)(b0 + 0) * NG_ + warp * 16) * H32_ + lane;
        const float* up1 = g_up + ((size_t)(b0 + 1) * NG_ + warp * 16) * H32_ + lane;
        float ua0 = 0.f, ua1 = 0.f, ub0 = 0.f, ub1 = 0.f;
#pragma unroll
        for (int k = 0; k < 16; k += 2) {
            ua0 += up0[(size_t)(k + 0) * H32_];
            ua1 += up0[(size_t)(k + 1) * H32_];
            ub0 += up1[(size_t)(k + 0) * H32_];
            ub1 += up1[(size_t)(k + 1) * H32_];
        }
        s_p[0][warp][lane] = p0 + (ua0 + ua1);
        s_p[1][warp][lane] = p1 + (ub0 + ub1);
    }
    __syncthreads();

    // ---- LSTM: warp q in {0,1}; z = bvec + partial sums ----
    if (warp < 2) {
        float z = g_bvec[lane];
#pragma unroll
        for (int w2 = 0; w2 < 8; w2++) z += s_p[warp][w2][lane];
        float zi = lb[lane];
        float zg = lb[64 + lane];
        float zo = lb[96 + lane];
#pragma unroll
        for (int m = 0; m < 32; m++) {
            float v = __shfl_sync(0xffffffffu, z, m);
            zi += v * lk[m * 128 + lane];
            zg += v * lk[m * 128 + 64 + lane];
            zo += v * lk[m * 128 + 96 + lane];
        }
        float ig = 1.0f / (1.0f + expf(-zi));
        float gg = tanhf(zg);
        float og = 1.0f / (1.0f + expf(-zo));
        float c  = ig * gg;
        float h  = og * tanhf(c);
        s_q[warp][lane] = h;
        float part = b_conv[lane] * h;
#pragma unroll
        for (int s = 16; s > 0; s >>= 1) part += __shfl_xor_sync(0xffffffffu, part, s);
        if (lane == 0) s_c0[warp] = part;
    }
    __syncthreads();

    // ---- w = W_conv @ q, row per thread, shared across both b's ----
    {
        const float* wr = W_conv + tid * H32_;
        float4 wc[8];
#pragma unroll
        for (int m = 0; m < 8; m++) wc[m] = *(const float4*)(wr + m * 4);
#pragma unroll
        for (int q = 0; q < 2; q++) {
            float s0 = 0.f, s1 = 0.f;
#pragma unroll
            for (int m = 0; m < 8; m++) {
                s0 += wc[m].x * s_q[q][m * 4 + 0] + wc[m].y * s_q[q][m * 4 + 1];
                s1 += wc[m].z * s_q[q][m * 4 + 2] + wc[m].w * s_q[q][m * 4 + 3];
            }
            s_w[q][tid] = s0 + s1;
        }
    }
    __syncthreads();

    // =========================== Stream both b's ===========================
    for (int q = 0; q < 2; q++) {
        const int b = b0 + q;
        const float4 w0 = *(const float4*)(&s_w[q][4 * lane]);
        const float4 w1 = *(const float4*)(&s_w[q][128 + 4 * lane]);
        const float cb = s_c0[q];
        const int tm = tum[b];
        const float4* eb = (const float4*)(ee + (size_t)b * E_ * EMB_);

#pragma unroll
        for (int it = 0; it < 16; it++) {
            const int e0 = it * 32 + warp * 4;
            float4 r0a = __ldcs(eb + (size_t)(e0 + 0) * 64 + lane);
            float4 r0b = __ldcs(eb + (size_t)(e0 + 0) * 64 + 32 + lane);
            float4 r1a = __ldcs(eb + (size_t)(e0 + 1) * 64 + lane);
            float4 r1b = __ldcs(eb + (size_t)(e0 + 1) * 64 + 32 + lane);
            float4 r2a = __ldcs(eb + (size_t)(e0 + 2) * 64 + lane);
            float4 r2b = __ldcs(eb + (size_t)(e0 + 2) * 64 + 32 + lane);
            float4 r3a = __ldcs(eb + (size_t)(e0 + 3) * 64 + lane);
            float4 r3b = __ldcs(eb + (size_t)(e0 + 3) * 64 + 32 + lane);

            float s0 = r0a.x * w0.x + r0a.y * w0.y + r0a.z * w0.z + r0a.w * w0.w
                     + r0b.x * w1.x + r0b.y * w1.y + r0b.z * w1.z + r0b.w * w1.w;
            float s1 = r1a.x * w0.x + r1a.y * w0.y + r1a.z * w0.z + r1a.w * w0.w
                     + r1b.x * w1.x + r1b.y * w1.y + r1b.z * w1.z + r1b.w * w1.w;
            float s2 = r2a.x * w0.x + r2a.y * w0.y + r2a.z * w0.z + r2a.w * w0.w
                     + r2b.x * w1.x + r2b.y * w1.y + r2b.z * w1.z + r2b.w * w1.w;
            float s3 = r3a.x * w0.x + r3a.y * w0.y + r3a.z * w0.z + r3a.w * w0.w
                     + r3b.x * w1.x + r3b.y * w1.y + r3b.z * w1.z + r3b.w * w1.w;
#pragma unroll
            for (int o = 16; o > 0; o >>= 1) {
                s0 += __shfl_xor_sync(0xffffffffu, s0, o);
                s1 += __shfl_xor_sync(0xffffffffu, s1, o);
                s2 += __shfl_xor_sync(0xffffffffu, s2, o);
                s3 += __shfl_xor_sync(0xffffffffu, s3, o);
            }
            if (lane == 0) {
                ys[e0 + 0] = s0 + cb;
                ys[e0 + 1] = s1 + cb;
                ys[e0 + 2] = s2 + cb;
                ys[e0 + 3] = s3 + cb;
            }
        }
        __syncthreads();

        const float y0 = ys[tid];
        const float y1 = ys[tid + 256];

        // masked logit stores: fire-and-forget
        const float mf = (float)tm;
        out[(size_t)b * 512 + tid]       = y0 * mf;
        out[(size_t)b * 512 + tid + 256] = y1 * mf;

        // gumbel noise (pure ALU)
        const float gb0 = gumbel_from_index((uint32_t)(b * 512 + tid));
        const float gb1 = gumbel_from_index((uint32_t)(b * 512 + tid + 256));

        // ---- max ----
        float m = fmaxf(y0, y1);
#pragma unroll
        for (int o = 16; o > 0; o >>= 1) m = fmaxf(m, __shfl_xor_sync(0xffffffffu, m, o));
        if (lane == 0) wred[warp] = m;
        __syncthreads();
        float maxv = wred[0];
#pragma unroll
        for (int i2 = 1; i2 < 8; i2++) maxv = fmaxf(maxv, wred[i2]);

        // ---- exp + sum ----
        const float e0v = expf(y0 - maxv);
        const float e1v = expf(y1 - maxv);
        float s = e0v + e1v;
#pragma unroll
        for (int o = 16; o > 0; o >>= 1) s += __shfl_xor_sync(0xffffffffu, s, o);
        if (lane == 0) wred2[warp] = s;
        __syncthreads();
        float sumv = wred2[0];
#pragma unroll
        for (int i2 = 1; i2 < 8; i2++) sumv += wred2[i2];

        if (mode != 0) {
            const float sc0 = e0v / sumv + gb0;
            const float sc1 = e1v / sumv + gb1;
            float bv; int bi;
            if (sc1 > sc0) { bv = sc1; bi = tid + 256; } else { bv = sc0; bi = tid; }
#pragma unroll
            for (int o = 16; o > 0; o >>= 1) {
                float ov = __shfl_xor_sync(0xffffffffu, bv, o);
                int   oi = __shfl_xor_sync(0xffffffffu, bi, o);
                if (ov > bv || (ov == bv && oi < bi)) { bv = ov; bi = oi; }
            }
            if (lane == 0) { wv[warp] = bv; wi[warp] = bi; }
            __syncthreads();
            if (tid == 0) {
                float fv = wv[0]; int fi = wi[0];
#pragma unroll
                for (int i2 = 1; i2 < 8; i2++) {
                    if (wv[i2] > fv || (wv[i2] == fv && wi[i2] < fi)) { fv = wv[i2]; fi = wi[i2]; }
                }
                long long id = (long long)fi * (long long)tm;
                if (mode == 1) out[1048576 + b] = (float)id;
                else ((long long*)(out + 1048576))[b] = id;
            }
        }
        __syncthreads();   // protect ys / wred reuse for next q
    }
}

// ---------------------------------------------------------------------------
extern "C" void kernel_launch(void* const* d_in, const int* in_sizes, int n_in,
                              void* d_out, int out_size) {
    const float* ar     = (const float*)d_in[0];
    const int*   utm    = (const int*)d_in[1];
    const int*   tum    = (const int*)d_in[2];
    const float* ee     = (const float*)d_in[3];
    const float* W_func = (const float*)d_in[4];
    const float* b_func = (const float*)d_in[5];
    const float* W_conv = (const float*)d_in[6];
    const float* b_conv = (const float*)d_in[7];
    const float* W_fc1  = (const float*)d_in[8];
    const float* b_fc1  = (const float*)d_in[9];
    const float* W_fc2  = (const float*)d_in[10];
    const float* b_fc2  = (const float*)d_in[11];
    const float* lk     = (const float*)d_in[12];
    // d_in[13] = lstm_recurrent: unused (h0 = 0)
    const float* lb     = (const float*)d_in[14];

    kernelJ<<<512, 256>>>(ar, utm, W_func, b_func, W_fc1, W_fc2, b_fc1, b_fc2);

    int mode = 0;
    if (out_size >= 1048576 + 4096)      mode = 2;
    else if (out_size >= 1048576 + 2048) mode = 1;
    kernelBFS2<<<1024, 256>>>(tum, ee, W_conv, b_conv, W_fc2,
                              lk, lb, (float*)d_out, mode);
}